// round 14
// baseline (speedup 1.0000x reference)
#include <cuda_runtime.h>
#include <cuda_fp16.h>
#include <cstdint>

// Problem dims (fixed by the dataset)
#define SEQ  2048
#define OUTF 8192
#define INF  8192

// Scratch (device globals are the sanctioned no-cudaMalloc scratch)
__device__ __half g_Wh[(size_t)OUTF * INF];   // 128 MiB dequantized weights, [O][K]
__device__ __half g_Xh[(size_t)SEQ  * INF];   //  32 MiB fp16 activations,   [S][K]

// ---------------------------------------------------------------------------
// PTX helpers — baseline (non-'a') ISA only: cp.async / ldmatrix / mma.sync
// ---------------------------------------------------------------------------
__device__ __forceinline__ uint32_t smem_u32(const void* p) {
    uint32_t r;
    asm("{ .reg .u64 t; cvta.to.shared.u64 t, %1; cvt.u32.u64 %0, t; }"
        : "=r"(r) : "l"(p));
    return r;
}

__device__ __forceinline__ void cp16(uint32_t saddr, const void* g) {
    asm volatile("cp.async.cg.shared.global [%0], [%1], 16;"
                 :: "r"(saddr), "l"(g) : "memory");
}
__device__ __forceinline__ void cp_commit() {
    asm volatile("cp.async.commit_group;" ::: "memory");
}
template <int N>
__device__ __forceinline__ void cp_wait() {
    asm volatile("cp.async.wait_group %0;" :: "n"(N) : "memory");
}

#define LDSM4(r, addr) \
    asm volatile("ldmatrix.sync.aligned.m8n8.x4.shared.b16 {%0,%1,%2,%3}, [%4];" \
                 : "=r"((r)[0]), "=r"((r)[1]), "=r"((r)[2]), "=r"((r)[3])        \
                 : "r"(addr))

#define MMA16816(d, a, b0, b1)                                                  \
    asm volatile("mma.sync.aligned.m16n8k16.row.col.f32.f16.f16.f32 "           \
                 "{%0,%1,%2,%3}, {%4,%5,%6,%7}, {%8,%9}, {%0,%1,%2,%3};"        \
                 : "+f"((d)[0]), "+f"((d)[1]), "+f"((d)[2]), "+f"((d)[3])       \
                 : "r"((a)[0]), "r"((a)[1]), "r"((a)[2]), "r"((a)[3]),          \
                   "r"(b0), "r"(b1))

// ---------------------------------------------------------------------------
// Fused prep kernel (heterogeneous grid):
//   blocks [0, 1024)        : dequant qweight -> g_Wh via per-row pair LUT
//   blocks [1024, 1024+4096): x fp32 -> fp16 into g_Xh (4 float4 per thread)
// ---------------------------------------------------------------------------
#define DQ_BLOCKS  (OUTF / 8)                 // 1024
#define CVT_BLOCKS ((SEQ * INF / 4) / 1024)   // 4096
#define PREP_GRID  (DQ_BLOCKS + CVT_BLOCKS)   // 5120

__device__ __forceinline__ void dq_word(uint32_t wd, const uint32_t* pl,
                                        uint32_t& a, uint32_t& b) {
    uint32_t t = (wd >> 4) & 0x0F0F0F0Fu;  // byte c = idx_c (top nibble of code c)
    uint32_t u = t | (t >> 4);             // byte0 = idx0|idx1<<4, byte2 = idx2|idx3<<4
    a = pl[u & 0xFFu];
    b = pl[(u >> 16) & 0xFFu];
}

__global__ void __launch_bounds__(256) prep_kernel(const float* __restrict__ x,
                                                   const int* __restrict__ qw,
                                                   const float* __restrict__ lutp) {
    __shared__ uint32_t plut[8][256];
    const int bid = blockIdx.x;
    const int tid = threadIdx.x;

    if (bid < DQ_BLOCKS) {
        // ---- dequant branch ----
        const int w = tid >> 5, lid = tid & 31;
        const int row = bid * 8 + w;

        float lv = lutp[row * 16 + (lid & 15)];
        #pragma unroll
        for (int e = lid; e < 256; e += 32) {
            float lo = __shfl_sync(0xffffffffu, lv, e & 15);
            float hi = __shfl_sync(0xffffffffu, lv, (e >> 4) & 15);
            __half2 h = __floats2half2_rn(lo, hi);
            plut[w][e] = *reinterpret_cast<uint32_t*>(&h);
        }
        __syncwarp();

        const int4* qrow = reinterpret_cast<const int4*>(qw) + (size_t)row * (INF / 16);
        int4* orow = reinterpret_cast<int4*>(g_Wh + (size_t)row * INF);
        const uint32_t* pl = plut[w];

        #pragma unroll 4
        for (int i = lid; i < INF / 16; i += 32) {   // 512 int4 words per row
            int4 q = qrow[i];
            uint32_t o0, o1, o2, o3, o4, o5, o6, o7;
            dq_word((uint32_t)q.x, pl, o0, o1);
            dq_word((uint32_t)q.y, pl, o2, o3);
            dq_word((uint32_t)q.z, pl, o4, o5);
            dq_word((uint32_t)q.w, pl, o6, o7);
            orow[2 * i]     = make_int4((int)o0, (int)o1, (int)o2, (int)o3);
            orow[2 * i + 1] = make_int4((int)o4, (int)o5, (int)o6, (int)o7);
        }
    } else {
        // ---- fp32 -> fp16 convert branch ----
        const int cb = bid - DQ_BLOCKS;              // 0 .. 4095
        const int base = cb * 1024;                  // float4 units
        #pragma unroll
        for (int j = 0; j < 4; j++) {
            int i = base + j * 256 + tid;
            float4 v = reinterpret_cast<const float4*>(x)[i];
            __half2 a = __floats2half2_rn(v.x, v.y);
            __half2 b = __floats2half2_rn(v.z, v.w);
            uint2 st = make_uint2(*reinterpret_cast<uint32_t*>(&a),
                                  *reinterpret_cast<uint32_t*>(&b));
            reinterpret_cast<uint2*>(g_Xh)[i] = st;
        }
    }
}

// ---------------------------------------------------------------------------
// GEMM: out[m][n] = sum_k Xh[m][k]*Wh[n][k]
//   Persistent grid (296 CTAs), CTA 128x128x32, 4 warps (64x64 warp tile),
//   2 CTAs/SM, 5-stage cp.async, RSTR=40 pad (conflict-free ldmatrix).
//   R14: per-kt body restructured for overlap — all 16 LDSM4 hoisted to the
//   top (separate a0/b0/a1/b1 frags so ks1 loads fly under ks0 MMAs), and
//   the next-stage cp.async issue moved BEFORE the MMA chain.
// ---------------------------------------------------------------------------
#define BM 128
#define BN 128
#define BK 32
#define NSTG 5
#define RSTR 40                         // halves per padded row
#define A_ELE (BM * RSTR)               // 5120 halves
#define B_ELE (BN * RSTR)               // 5120 halves
#define STG_ELE (A_ELE + B_ELE)         // 10240 halves (20 KB)
#define SMEM_BYTES (NSTG * STG_ELE * 2) // 102400 B per CTA (x2 = 200 KB/SM)
#define NK (INF / BK)                   // 256 k-iters
#define NTILE_N (OUTF / BN)             // 64
#define NTILES  (NTILE_N * (SEQ / BM))  // 1024
#define GRID_CTAS 296                   // 2 CTAs/SM x 148 SMs

__global__ void __launch_bounds__(128, 2) gemm_kernel(float* __restrict__ out) {
    extern __shared__ __half sm[];
    const uint32_t sbase = smem_u32(sm);
    const int tid = threadIdx.x;
    const int wid = tid >> 5, lane = tid & 31;
    const int wm = (wid & 1) * 64;       // warp tile M offset in CTA
    const int wn = (wid >> 1) * 64;      // warp tile N offset in CTA

    // ldmatrix per-lane row/col-chunk mapping (matches m16n8k16 frag layouts)
    const int a_row = ((lane >> 3) & 1) * 8 + (lane & 7);  // + kc = lane>>4
    const int a_kc  = lane >> 4;
    const int b_row = ((lane >> 4) << 3) + (lane & 7);     // + kc = (lane>>3)&1
    const int b_kc  = (lane >> 3) & 1;

    uint32_t sA[4], sB[4];
    #pragma unroll
    for (int i = 0; i < 4; i++) {
        int idx = tid + i * 128;
        int r = idx >> 2, c = idx & 3;
        sA[i] = (uint32_t)(r * RSTR + c * 8) * 2;
        sB[i] = (uint32_t)(A_ELE + r * RSTR + c * 8) * 2;
    }
    const int er = lane >> 2, ec = (lane & 3) * 2;         // epilogue lane map

    #pragma unroll 1
    for (int t = blockIdx.x; t < NTILES; t += GRID_CTAS) {
        const int n0 = (t % NTILE_N) * BN;   // N fast
        const int m0 = (t / NTILE_N) * BM;

        // make smem safe for reuse (prior tile's reads / cp groups done)
        cp_wait<0>();
        __syncthreads();

        const __half* gA[4]; const __half* gB[4];
        #pragma unroll
        for (int i = 0; i < 4; i++) {
            int idx = tid + i * 128;
            int r = idx >> 2, c = idx & 3;
            gA[i] = g_Xh + (size_t)(m0 + r) * INF + c * 8;
            gB[i] = g_Wh + (size_t)(n0 + r) * INF + c * 8;
        }

        float acc[4][8][4];
        #pragma unroll
        for (int mi = 0; mi < 4; mi++)
            #pragma unroll
            for (int nj = 0; nj < 8; nj++)
                acc[mi][nj][0] = acc[mi][nj][1] = acc[mi][nj][2] = acc[mi][nj][3] = 0.f;

        auto issue = [&](int kt, int s) {
            const uint32_t so = sbase + (uint32_t)(s * STG_ELE) * 2;
            const int ko = kt * BK;
            #pragma unroll
            for (int i = 0; i < 4; i++) {
                cp16(so + sA[i], gA[i] + ko);
                cp16(so + sB[i], gB[i] + ko);
            }
        };

        #pragma unroll
        for (int s = 0; s < NSTG - 1; s++) { issue(s, s); cp_commit(); }

        #pragma unroll 1
        for (int kt = 0; kt < NK; kt++) {
            cp_wait<NSTG - 2>();
            __syncthreads();

            const uint32_t sa = sbase + (uint32_t)((kt % NSTG) * STG_ELE) * 2;
            const uint32_t sb = sa + (uint32_t)A_ELE * 2;

            // ---- hoist ALL fragment loads: ks1 loads overlap ks0 MMAs ----
            uint32_t a0[4][4], b0[4][4], a1[4][4], b1[4][4];
            #pragma unroll
            for (int mi = 0; mi < 4; mi++)
                LDSM4(a0[mi], sa + (uint32_t)((wm + mi * 16 + a_row) * RSTR
                                              + a_kc * 8) * 2);
            #pragma unroll
            for (int p = 0; p < 4; p++)
                LDSM4(b0[p], sb + (uint32_t)((wn + p * 16 + b_row) * RSTR
                                             + b_kc * 8) * 2);
            #pragma unroll
            for (int mi = 0; mi < 4; mi++)
                LDSM4(a1[mi], sa + (uint32_t)((wm + mi * 16 + a_row) * RSTR
                                              + 16 + a_kc * 8) * 2);
            #pragma unroll
            for (int p = 0; p < 4; p++)
                LDSM4(b1[p], sb + (uint32_t)((wn + p * 16 + b_row) * RSTR
                                             + 16 + b_kc * 8) * 2);

            // ---- issue next stage early: cp.async flies under the MMAs ----
            const int nk = kt + NSTG - 1;
            if (nk < NK) issue(nk, nk % NSTG);
            cp_commit();

            #pragma unroll
            for (int mi = 0; mi < 4; mi++)
                #pragma unroll
                for (int nj = 0; nj < 8; nj++)
                    MMA16816(acc[mi][nj], a0[mi],
                             b0[nj >> 1][(nj & 1) * 2], b0[nj >> 1][(nj & 1) * 2 + 1]);
            #pragma unroll
            for (int mi = 0; mi < 4; mi++)
                #pragma unroll
                for (int nj = 0; nj < 8; nj++)
                    MMA16816(acc[mi][nj], a1[mi],
                             b1[nj >> 1][(nj & 1) * 2], b1[nj >> 1][(nj & 1) * 2 + 1]);
        }

        // Epilogue: c0,c1 -> (row lane/4, col (lane%4)*2); c2,c3 -> row+8
        #pragma unroll
        for (int mi = 0; mi < 4; mi++) {
            #pragma unroll
            for (int nj = 0; nj < 8; nj++) {
                float* p = out + (size_t)(m0 + wm + mi * 16 + er) * OUTF
                               + (n0 + wn + nj * 8 + ec);
                *reinterpret_cast<float2*>(p) =
                    make_float2(acc[mi][nj][0], acc[mi][nj][1]);
                *reinterpret_cast<float2*>(p + 8 * OUTF) =
                    make_float2(acc[mi][nj][2], acc[mi][nj][3]);
            }
        }
    }
}

// ---------------------------------------------------------------------------
extern "C" void kernel_launch(void* const* d_in, const int* in_sizes, int n_in,
                              void* d_out, int out_size) {
    const float* x   = (const float*)d_in[0];   // (1, 2048, 8192) fp32
    const int*   qw  = (const int*)  d_in[1];   // (8192, 2048)    int32
    const float* lut = (const float*)d_in[2];   // (8192, 16)      fp32
    float* out = (float*)d_out;                 // (1, 2048, 8192) fp32

    cudaFuncSetAttribute(gemm_kernel,
                         cudaFuncAttributeMaxDynamicSharedMemorySize, SMEM_BYTES);

    prep_kernel<<<PREP_GRID, 256>>>(x, qw, lut);
    gemm_kernel<<<GRID_CTAS, 128, SMEM_BYTES>>>(out);
}